// round 4
// baseline (speedup 1.0000x reference)
#include <cuda_runtime.h>
#include <cstdint>

// out[N,128] = segment_sum over edges: out[rows[e], :] += vals[e] * support[cols[e], :]
// One edge per warp: each lane handles one float4 (4 feats) -> warp covers F=128.
// Gather via LDG.128 (support is 51.2MB, L2-resident on the 126MB L2).
// Scatter via red.global.add.v4.f32 (no-return vector reduction, 4x fewer atomic ops).
// NOTE: indices are int32 (JAX x64 disabled downgrades jnp.int64 -> int32).

#define D_FEAT 128

__global__ void zero_out_kernel(float4* __restrict__ out, int n4) {
    int i = blockIdx.x * blockDim.x + threadIdx.x;
    if (i < n4) out[i] = make_float4(0.f, 0.f, 0.f, 0.f);
}

__global__ __launch_bounds__(256) void spmm_coo_kernel(
    const float* __restrict__ support,
    const float* __restrict__ vals,
    const int* __restrict__ rows,
    const int* __restrict__ cols,
    float* __restrict__ out,
    int n_edges)
{
    int warp = (blockIdx.x * blockDim.x + threadIdx.x) >> 5;
    int lane = threadIdx.x & 31;
    if (warp >= n_edges) return;

    int   r = __ldg(rows + warp);
    int   c = __ldg(cols + warp);
    float v = __ldg(vals + warp);

    const float4* src = reinterpret_cast<const float4*>(support + (long long)c * D_FEAT);
    float4 f = __ldg(src + lane);
    f.x *= v; f.y *= v; f.z *= v; f.w *= v;

    float* dst = out + (long long)r * D_FEAT + lane * 4;
    asm volatile("red.global.add.v4.f32 [%0], {%1, %2, %3, %4};"
                 :: "l"(dst), "f"(f.x), "f"(f.y), "f"(f.z), "f"(f.w)
                 : "memory");
}

extern "C" void kernel_launch(void* const* d_in, const int* in_sizes, int n_in,
                              void* d_out, int out_size) {
    const float* support = (const float*)d_in[0];
    const float* vals    = (const float*)d_in[1];
    const int*   rows    = (const int*)d_in[2];
    const int*   cols    = (const int*)d_in[3];
    float* out = (float*)d_out;

    int n_edges = in_sizes[1];

    // Zero the output (harness poisons it to 0xAA)
    int n4 = out_size / 4;
    zero_out_kernel<<<(n4 + 255) / 256, 256>>>((float4*)out, n4);

    // One warp per edge
    long long total_threads = (long long)n_edges * 32;
    int threads = 256;
    int blocks = (int)((total_threads + threads - 1) / threads);
    spmm_coo_kernel<<<blocks, threads>>>(support, vals, rows, cols, out, n_edges);
}

// round 7
// speedup vs baseline: 1.3308x; 1.3308x over previous
#include <cuda_runtime.h>
#include <cstdint>

// out[N,128] = segment_sum over edges: out[rows[e], :] += vals[e] * support[cols[e], :]
// 8 edges per warp: lanes 0-7 load the 8 edges' metadata (coalesced), broadcast
// via shfl, issue all 8 gather LDG.128s (MLP=8), then 8 RED.128 scatters.
// Indices are int32 (JAX x64-disabled downgrades int64 -> int32).

#define D_FEAT 128
#define EPW 8

__global__ void zero_out_kernel(float4* __restrict__ out, int n4) {
    int i = blockIdx.x * blockDim.x + threadIdx.x;
    if (i < n4) out[i] = make_float4(0.f, 0.f, 0.f, 0.f);
}

__device__ __forceinline__ void red_v4(float* dst, float4 f) {
    asm volatile("red.global.add.v4.f32 [%0], {%1, %2, %3, %4};"
                 :: "l"(dst), "f"(f.x), "f"(f.y), "f"(f.z), "f"(f.w)
                 : "memory");
}

__global__ __launch_bounds__(256) void spmm_coo_kernel(
    const float* __restrict__ support,
    const float* __restrict__ vals,
    const int* __restrict__ rows,
    const int* __restrict__ cols,
    float* __restrict__ out,
    int n_edges)
{
    int warp = (blockIdx.x * blockDim.x + threadIdx.x) >> 5;
    int lane = threadIdx.x & 31;
    long long base = (long long)warp * EPW;
    if (base >= n_edges) return;

    // Lanes 0..EPW-1 load edge metadata for this warp's 8 edges (32B coalesced)
    int r = 0, c = 0;
    float v = 0.f;
    if (lane < EPW) {
        long long e = base + lane;
        if (e < n_edges) {
            r = __ldg(rows + e);
            c = __ldg(cols + e);
            v = __ldg(vals + e);
        }
    }

    if (base + EPW <= n_edges) {
        // Fast path: all 8 edges valid. Issue all gathers first (MLP=8).
        float4 f[EPW];
        #pragma unroll
        for (int k = 0; k < EPW; k++) {
            int   ck = __shfl_sync(0xFFFFFFFFu, c, k);
            float vk = __shfl_sync(0xFFFFFFFFu, v, k);
            f[k] = __ldg(reinterpret_cast<const float4*>(
                            support + (long long)ck * D_FEAT) + lane);
            f[k].x *= vk; f[k].y *= vk; f[k].z *= vk; f[k].w *= vk;
        }
        #pragma unroll
        for (int k = 0; k < EPW; k++) {
            int rk = __shfl_sync(0xFFFFFFFFu, r, k);
            red_v4(out + (long long)rk * D_FEAT + lane * 4, f[k]);
        }
    } else {
        // Tail: guard each edge
        #pragma unroll
        for (int k = 0; k < EPW; k++) {
            if (base + k >= n_edges) break;
            int   ck = __shfl_sync(0xFFFFFFFFu, c, k);
            float vk = __shfl_sync(0xFFFFFFFFu, v, k);
            int   rk = __shfl_sync(0xFFFFFFFFu, r, k);
            float4 f = __ldg(reinterpret_cast<const float4*>(
                                support + (long long)ck * D_FEAT) + lane);
            f.x *= vk; f.y *= vk; f.z *= vk; f.w *= vk;
            red_v4(out + (long long)rk * D_FEAT + lane * 4, f);
        }
    }
}

extern "C" void kernel_launch(void* const* d_in, const int* in_sizes, int n_in,
                              void* d_out, int out_size) {
    const float* support = (const float*)d_in[0];
    const float* vals    = (const float*)d_in[1];
    const int*   rows    = (const int*)d_in[2];
    const int*   cols    = (const int*)d_in[3];
    float* out = (float*)d_out;

    int n_edges = in_sizes[1];

    // Zero the output (harness poisons it to 0xAA)
    int n4 = out_size / 4;
    zero_out_kernel<<<(n4 + 255) / 256, 256>>>((float4*)out, n4);

    // 8 edges per warp
    long long n_warps = ((long long)n_edges + EPW - 1) / EPW;
    long long total_threads = n_warps * 32;
    int threads = 256;
    int blocks = (int)((total_threads + threads - 1) / threads);
    spmm_coo_kernel<<<blocks, threads>>>(support, vals, rows, cols, out, n_edges);
}